// round 1
// baseline (speedup 1.0000x reference)
#include <cuda_runtime.h>

// PytorchLUTFakeQuant: t = clip(x * 64, -128, 127); snap to nearest of 16
// sorted integer centers (ties -> lower index); out = center * (2/128).
//
// Memory-bound elementwise op: 12,845,056 fp32 in -> fp32 out.
// float4 vectorization, centers in registers, branchless select chain.

static constexpr int NC = 16;

__global__ void __launch_bounds__(256, 8)
lut_fakequant_kernel(const float4* __restrict__ x,
                     const float* __restrict__ centers,
                     float4* __restrict__ out,
                     int n4) {
    __shared__ float sc[NC];
    if (threadIdx.x < NC) sc[threadIdx.x] = centers[threadIdx.x];
    __syncthreads();

    // Centers + midpoints into registers (constant-indexed throughout).
    float cv[NC];
#pragma unroll
    for (int i = 0; i < NC; i++) cv[i] = sc[i];
    float mid[NC - 1];
#pragma unroll
    for (int i = 0; i < NC - 1; i++) mid[i] = 0.5f * (cv[i] + cv[i + 1]);

    int idx = blockIdx.x * blockDim.x + threadIdx.x;
    if (idx >= n4) return;

    float4 v = x[idx];
    float4 r;

    // Branchless nearest-center: walk the 15 midpoints; strict '>' matches
    // argmin's lower-index tie-break. Final scale 2/128 = 1/64 (exact).
#define QUANT_ONE(IN, OUT)                                    \
    do {                                                      \
        float t = fminf(fmaxf((IN) * 64.0f, -128.0f), 127.0f);\
        float res = cv[0];                                    \
        _Pragma("unroll")                                     \
        for (int i = 0; i < NC - 1; i++)                      \
            res = (t > mid[i]) ? cv[i + 1] : res;             \
        (OUT) = res * 0.015625f;                              \
    } while (0)

    QUANT_ONE(v.x, r.x);
    QUANT_ONE(v.y, r.y);
    QUANT_ONE(v.z, r.z);
    QUANT_ONE(v.w, r.w);
#undef QUANT_ONE

    out[idx] = r;
}

extern "C" void kernel_launch(void* const* d_in, const int* in_sizes, int n_in,
                              void* d_out, int out_size) {
    // Inputs: x (12,845,056 fp32), cluster_centers (16 fp32). Be robust to order.
    const float* x = (const float*)d_in[0];
    const float* centers = (const float*)d_in[1];
    if (n_in >= 2 && in_sizes[0] == NC && in_sizes[1] != NC) {
        x = (const float*)d_in[1];
        centers = (const float*)d_in[0];
    }

    int n4 = out_size / 4;  // 12,845,056 / 4 = 3,211,264 (exact)
    int threads = 256;
    int blocks = (n4 + threads - 1) / threads;

    lut_fakequant_kernel<<<blocks, threads>>>(
        (const float4*)x, centers, (float4*)d_out, n4);

    // Handle any non-multiple-of-4 tail (not expected for this shape, but safe).
    int tail = out_size - n4 * 4;
    if (tail > 0) {
        // Reuse the same kernel on the last partial quartet is unsafe; do a
        // tiny dedicated launch instead. (Dead code for this problem's shape.)
        // No-op here since out_size % 4 == 0 for 32*128*56*56.
    }
}

// round 2
// speedup vs baseline: 1.6481x; 1.6481x over previous
#include <cuda_runtime.h>

// PytorchLUTFakeQuant: t = clip(x*64, -128, 127); nearest of 16 sorted
// INTEGER centers (tie -> lower index); out = center / 64.
//
// Trick: midpoints m_i = c_i + c_{i+1} are integers in 2t-space.
// With u = clip(x*128, -256, 254):  count(m_i < u) == count(m_i <= ceil(u)-1)
// exactly (ties excluded, matching argmin lower-index tie-break).
// -> 511-entry shared LUT indexed by ceil(u)+256. One F2I + one LDS per elem.

static constexpr int NC = 16;
static constexpr int LUT_SIZE = 512;          // indices 0..510 used
static constexpr int BLOCK = 256;
static constexpr int V_PER_THREAD = 4;        // 4 x float4 = 16 floats/thread

__global__ void __launch_bounds__(BLOCK, 8)
lut_fakequant_kernel(const float4* __restrict__ x,
                     const float* __restrict__ centers,
                     float4* __restrict__ out,
                     int n4) {
    __shared__ float lut[LUT_SIZE];

    // ---- Build LUT (amortized over 16 elems/thread) ----
    // Every thread reads all 16 centers (L1 broadcast).
    float cv[NC];
#pragma unroll
    for (int i = 0; i < NC; i++) cv[i] = __ldg(&centers[i]);
    float m[NC - 1];
#pragma unroll
    for (int i = 0; i < NC - 1; i++) m[i] = cv[i] + cv[i + 1];  // integer, exact

    // lut[k] = cv[ #{ m_i <= k-257 } ] / 64
#pragma unroll
    for (int e = 0; e < LUT_SIZE / BLOCK; e++) {
        int k = threadIdx.x + e * BLOCK;
        float idxval = (float)(k - 257);      // exact for |v| <= 257
        int count = 0;
#pragma unroll
        for (int i = 0; i < NC - 1; i++) count += (m[i] <= idxval);
        lut[k] = cv[count] * 0.015625f;       // 1/64, exact
    }
    __syncthreads();

    // ---- Main loop: 4 float4 per thread, block-strided for coalescing ----
    int base = blockIdx.x * (BLOCK * V_PER_THREAD) + threadIdx.x;

    float4 v[V_PER_THREAD];
#pragma unroll
    for (int k = 0; k < V_PER_THREAD; k++) {
        int i = base + k * BLOCK;
        if (i < n4) v[k] = x[i];              // front-batched LDGs (MLP=4)
    }

#pragma unroll
    for (int k = 0; k < V_PER_THREAD; k++) {
        int i = base + k * BLOCK;
        if (i >= n4) continue;
        float4 r;
#define QUANT_ONE(IN, OUT)                                          \
        do {                                                        \
            float u = fminf(fmaxf((IN) * 128.0f, -256.0f), 254.0f); \
            int ki = __float2int_ru(u) + 256;                       \
            (OUT) = lut[ki];                                        \
        } while (0)
        QUANT_ONE(v[k].x, r.x);
        QUANT_ONE(v[k].y, r.y);
        QUANT_ONE(v[k].z, r.z);
        QUANT_ONE(v[k].w, r.w);
#undef QUANT_ONE
        out[i] = r;
    }
}

extern "C" void kernel_launch(void* const* d_in, const int* in_sizes, int n_in,
                              void* d_out, int out_size) {
    const float* x = (const float*)d_in[0];
    const float* centers = (const float*)d_in[1];
    if (n_in >= 2 && in_sizes[0] == NC && in_sizes[1] != NC) {
        x = (const float*)d_in[1];
        centers = (const float*)d_in[0];
    }

    int n4 = out_size / 4;                    // 3,211,264 (exact multiple)
    int per_block = BLOCK * V_PER_THREAD;     // 1024 float4 per block
    int blocks = (n4 + per_block - 1) / per_block;   // 3136

    lut_fakequant_kernel<<<blocks, BLOCK>>>(
        (const float4*)x, centers, (float4*)d_out, n4);
}